// round 6
// baseline (speedup 1.0000x reference)
#include <cuda_runtime.h>
#include <cuda_fp16.h>
#include <cstdint>

// ---------------------------------------------------------------- constants
#define N_TOKENS  65536
#define IN_DIM    2048
#define N_EXPERTS 64
#define TILE_M    128
#define BK        32
#define NITER     (IN_DIM / BK)       // 64
#define NTHREADS  256
#define GRID_CTAS (N_TOKENS / TILE_M) // 512

// smem stage layout (bytes). Row stride 40 halves = 80 B (20 words):
// 20*r mod 32 distinct for r=0..7 -> conflict-free ldmatrix.
// [ A_h1 128x80 | A_h2 128x80 | B_w1 64x80 | B_w2 64x80 ]
#define OFF_AR    10240
#define OFF_B1    20480
#define OFF_B2    25600
#define STAGE_B   30720
#define SMEM_BYTES (2 * STAGE_B)      // 61440 -> 2 CTAs/SM = 120 KB

#define SPLIT_SCALE 2048.0f
#define INV_SCALE   (1.0f / 2048.0f)

// W pack: [chunk j=0..63][split 0..1][n=0..63][k=0..31] fp16 (512 KB)
// split0 = fp16(w), split1 = fp16((w - fp16(w)) * 2048)   (scaled: no subnormals)
__device__ __align__(16) __half Wpack_g[NITER * 2 * N_EXPERTS * BK];

// ---------------------------------------------------------------- helpers
__device__ __forceinline__ uint32_t smem_u32(const void* p) {
    uint32_t a;
    asm("{ .reg .u64 t; cvta.to.shared.u64 t, %1; cvt.u32.u64 %0, t; }" : "=r"(a) : "l"(p));
    return a;
}

__device__ __forceinline__ void ldsm4(uint32_t* r, uint32_t addr) {
    asm volatile("ldmatrix.sync.aligned.m8n8.x4.shared.b16 {%0,%1,%2,%3}, [%4];"
                 : "=r"(r[0]), "=r"(r[1]), "=r"(r[2]), "=r"(r[3]) : "r"(addr));
}

// fp32-accumulated main-bank MMA
__device__ __forceinline__ void mma_f32(float* c, const uint32_t* a,
                                        uint32_t b0, uint32_t b1) {
    asm volatile(
        "mma.sync.aligned.m16n8k16.row.col.f32.f16.f16.f32 "
        "{%0,%1,%2,%3}, {%4,%5,%6,%7}, {%8,%9}, {%0,%1,%2,%3};"
        : "+f"(c[0]), "+f"(c[1]), "+f"(c[2]), "+f"(c[3])
        : "r"(a[0]), "r"(a[1]), "r"(a[2]), "r"(a[3]), "r"(b0), "r"(b1));
}

// fp16-accumulated cross-bank MMA (2 C regs = 4 halves)
__device__ __forceinline__ void mma_f16(uint32_t* c, const uint32_t* a,
                                        uint32_t b0, uint32_t b1) {
    asm volatile(
        "mma.sync.aligned.m16n8k16.row.col.f16.f16.f16.f16 "
        "{%0,%1}, {%2,%3,%4,%5}, {%6,%7}, {%0,%1};"
        : "+r"(c[0]), "+r"(c[1])
        : "r"(a[0]), "r"(a[1]), "r"(a[2]), "r"(a[3]), "r"(b0), "r"(b1));
}

__device__ __forceinline__ void cp_async16(uint32_t dst, const void* src) {
    asm volatile("cp.async.ca.shared.global [%0], [%1], 16;" :: "r"(dst), "l"(src));
}
#define CP_COMMIT() asm volatile("cp.async.commit_group;" ::: "memory")
#define CP_WAIT0()  asm volatile("cp.async.wait_group 0;" ::: "memory")

// ---------------------------------------------------------------- W split pre-kernel
__global__ void wsplit_kernel(const float* __restrict__ W) {
    int idx = blockIdx.x * 256 + threadIdx.x;   // e*2048 + k
    int e = idx >> 11;
    int k = idx & 2047;
    float w = W[idx];
    __half h1 = __float2half_rn(w);
    float  r  = (w - __half2float(h1)) * SPLIT_SCALE;
    __half h2 = __float2half_rn(r);
    int j = k >> 5, kk = k & 31;
    Wpack_g[(size_t)j * 4096 + 0 * 2048 + e * 32 + kk] = h1;
    Wpack_g[(size_t)j * 4096 + 1 * 2048 + e * 32 + kk] = h2;
}

// ---------------------------------------------------------------- x conversion
// h1 = fp16(x); h2 = fp16((x - h1) * 2048)  -- scaled, stays in normal range
__device__ __forceinline__ void cvt_store(char* Ab, uint32_t off, float4 v) {
    __half2 h1a = __floats2half2_rn(v.x, v.y);
    __half2 h1b = __floats2half2_rn(v.z, v.w);
    float2 fa = __half22float2(h1a);
    float2 fb = __half22float2(h1b);
    __half2 ra = __floats2half2_rn((v.x - fa.x) * SPLIT_SCALE, (v.y - fa.y) * SPLIT_SCALE);
    __half2 rb = __floats2half2_rn((v.z - fb.x) * SPLIT_SCALE, (v.w - fb.y) * SPLIT_SCALE);
    uint2 hh, rr;
    hh.x = *(uint32_t*)&h1a; hh.y = *(uint32_t*)&h1b;
    rr.x = *(uint32_t*)&ra;  rr.y = *(uint32_t*)&rb;
    *(uint2*)(Ab + off)          = hh;
    *(uint2*)(Ab + OFF_AR + off) = rr;
}

// ---------------------------------------------------------------- main kernel
extern __shared__ __align__(16) char smch[];

__global__ void __launch_bounds__(NTHREADS, 2)
router_mma_kernel(const float* __restrict__ x, float* __restrict__ out) {
    const int tid  = threadIdx.x;
    const int w    = tid >> 5;
    const int lane = tid & 31;
    const int tokenBase = blockIdx.x * TILE_M;
    const uint32_t sb = smem_u32(smch);

    // ---- x LDG map: instr i covers rows w*16 + i*4 + (lane>>3), float4 (lane&7)
    //      -> each warp-LDG.128 touches 4 contiguous 128B lines.
    const float* xbase = x + (size_t)(tokenBase + w * 16 + (lane >> 3)) * IN_DIM
                           + (lane & 7) * 4;
    const uint32_t st_base = (uint32_t)((w * 16 + (lane >> 3)) * 80 + (lane & 7) * 8);

    // ---- W cp.async map
    const int wn  = (tid >> 2) & 63;
    const int wsk = tid & 3;
    const uint32_t b_dst0 = OFF_B1 + (uint32_t)wn * 80 + (uint32_t)wsk * 16;
    const uint32_t b_dst1 = OFF_B2 + (uint32_t)wn * 80 + (uint32_t)wsk * 16;

    // ---- ldmatrix offsets (stage-relative); warp owns rows [w*16, w*16+16)
    const uint32_t a_ld = (uint32_t)((w * 16 + (lane & 15)) * 80 + ((lane >> 4) & 1) * 16);
    const uint32_t b_ld = (uint32_t)(((lane & 7) + ((lane >> 4) & 1) * 8) * 80
                                     + ((lane >> 3) & 1) * 16);

    float    accM[32];    // fp32 main bank: h1*w1
    uint32_t accC[16];    // fp16 cross bank: h1*w2 + h2*w1 (cross units = x2048)
    #pragma unroll
    for (int i = 0; i < 32; i++) accM[i] = 0.0f;
    #pragma unroll
    for (int i = 0; i < 16; i++) accC[i] = 0u;

    float4 xr[4];

    // ================= prologue: fill stage 0 =================
    {
        const char* wsrc = (const char*)Wpack_g;
        cp_async16(sb + b_dst0, wsrc + (size_t)tid * 16);
        cp_async16(sb + b_dst1, wsrc + (size_t)(tid + 256) * 16);
        CP_COMMIT();
        #pragma unroll
        for (int i = 0; i < 4; i++)
            xr[i] = *(const float4*)(xbase + (size_t)i * 4 * IN_DIM);
        char* Ab = smch;
        #pragma unroll
        for (int i = 0; i < 4; i++)
            cvt_store(Ab, st_base + (uint32_t)i * 320, xr[i]);
        CP_WAIT0();
        __syncthreads();
    }

    // ================= main loop =================
    for (int j = 0; j < NITER; j++) {
        const int s  = j & 1;
        const int nx = s ^ 1;
        const uint32_t stage = (uint32_t)s * STAGE_B;

        if (j + 1 < NITER) {
            const char* wsrc = (const char*)Wpack_g + (size_t)(j + 1) * 8192;
            const uint32_t nst = (uint32_t)nx * STAGE_B;
            cp_async16(sb + nst + b_dst0, wsrc + (size_t)tid * 16);
            cp_async16(sb + nst + b_dst1, wsrc + (size_t)(tid + 256) * 16);
            CP_COMMIT();
            #pragma unroll
            for (int i = 0; i < 4; i++)
                xr[i] = *(const float4*)(xbase + (size_t)i * 4 * IN_DIM + (j + 1) * BK);
        }

        // ---- compute stage s ----
        #pragma unroll
        for (int kk = 0; kk < 2; kk++) {
            const uint32_t ko = (uint32_t)kk * 32;
            uint32_t aH[4], aG[4];
            ldsm4(aH, sb + stage + a_ld + ko);
            ldsm4(aG, sb + stage + OFF_AR + a_ld + ko);
            #pragma unroll
            for (int g = 0; g < 4; g++) {
                const uint32_t bo = b_ld + (uint32_t)g * 1280 + ko;
                uint32_t w1[4], w2[4];
                ldsm4(w1, sb + stage + OFF_B1 + bo);
                ldsm4(w2, sb + stage + OFF_B2 + bo);
                mma_f32(&accM[(2 * g) * 4],     aH, w1[0], w1[1]); // h1*w1
                mma_f32(&accM[(2 * g + 1) * 4], aH, w1[2], w1[3]);
                mma_f16(&accC[(2 * g) * 2],     aH, w2[0], w2[1]); // h1*w2
                mma_f16(&accC[(2 * g + 1) * 2], aH, w2[2], w2[3]);
                mma_f16(&accC[(2 * g) * 2],     aG, w1[0], w1[1]); // h2*w1
                mma_f16(&accC[(2 * g + 1) * 2], aG, w1[2], w1[3]);
            }
        }

        if (j + 1 < NITER) {
            char* Ab = smch + (size_t)nx * STAGE_B;
            #pragma unroll
            for (int i = 0; i < 4; i++)
                cvt_store(Ab, st_base + (uint32_t)i * 320, xr[i]);
            CP_WAIT0();
        }
        __syncthreads();
    }

    // ================= epilogue =================
    const int q  = lane >> 2;   // row-in-8
    const int qc = lane & 3;    // column quad slot
    float* outIdx = out;
    float* outW   = out + 2 * (size_t)N_TOKENS;
    float* probs  = out + 4 * (size_t)N_TOKENS;

    #pragma unroll
    for (int r = 0; r < 2; r++) {
        // logits = main + cross/2048
        float v[16];
        #pragma unroll
        for (int f = 0; f < 8; f++) {
            uint32_t cr = accC[f * 2 + r];
            float2 cf = __half22float2(*(__half2*)&cr);
            v[2 * f]     = fmaf(cf.x, INV_SCALE, accM[f * 4 + 2 * r]);
            v[2 * f + 1] = fmaf(cf.y, INV_SCALE, accM[f * 4 + 2 * r + 1]);
        }
        // quad max
        float mx = v[0];
        #pragma unroll
        for (int i = 1; i < 16; i++) mx = fmaxf(mx, v[i]);
        mx = fmaxf(mx, __shfl_xor_sync(0xffffffffu, mx, 1));
        mx = fmaxf(mx, __shfl_xor_sync(0xffffffffu, mx, 2));

        // local top-2 on logits (e ascending within lane)
        float v1 = -3.4e38f, v2 = -3.4e38f;
        int   i1 = 0, i2 = 0;
        #pragma unroll
        for (int f = 0; f < 8; f++) {
            #pragma unroll
            for (int c = 0; c < 2; c++) {
                float val = v[2 * f + c];
                int   e   = f * 8 + qc * 2 + c;
                if (val > v1)      { v2 = v1; i2 = i1; v1 = val; i1 = e; }
                else if (val > v2) { v2 = val; i2 = e; }
            }
        }
        // quad merge (tie -> lower index, matching jax)
        #pragma unroll
        for (int d = 1; d <= 2; d <<= 1) {
            float ov1 = __shfl_xor_sync(0xffffffffu, v1, d);
            int   oi1 = __shfl_xor_sync(0xffffffffu, i1, d);
            float ov2 = __shfl_xor_sync(0xffffffffu, v2, d);
            int   oi2 = __shfl_xor_sync(0xffffffffu, i2, d);
            bool bet1 = (ov1 > v1) || (ov1 == v1 && oi1 < i1);
            if (bet1) {
                bool keepOld = (v1 > ov2) || (v1 == ov2 && i1 < oi2);
                if (keepOld) { v2 = v1; i2 = i1; } else { v2 = ov2; i2 = oi2; }
                v1 = ov1; i1 = oi1;
            } else {
                bool bet2 = (ov1 > v2) || (ov1 == v2 && oi1 < i2);
                if (bet2) { v2 = ov1; i2 = oi1; }
            }
        }

        // exp + quad sum
        float ssum = 0.0f;
        #pragma unroll
        for (int i = 0; i < 16; i++) { v[i] = __expf(v[i] - mx); ssum += v[i]; }
        ssum += __shfl_xor_sync(0xffffffffu, ssum, 1);
        ssum += __shfl_xor_sync(0xffffffffu, ssum, 2);
        float rinv = 1.0f / ssum;

        const int row = tokenBase + w * 16 + q + r * 8;
        float* pr = probs + (size_t)row * N_EXPERTS + qc * 2;
        #pragma unroll
        for (int f = 0; f < 8; f++) {
            float2 pv = make_float2(v[2 * f] * rinv, v[2 * f + 1] * rinv);
            *(float2*)(pr + f * 8) = pv;
        }
        if (qc == 0) {
            float p1 = __expf(v1 - mx), p2 = __expf(v2 - mx);
            outIdx[(size_t)row * 2 + 0] = (float)i1;
            outIdx[(size_t)row * 2 + 1] = (float)i2;
            float tw = 1.0f / (p1 + p2);
            outW[(size_t)row * 2 + 0] = p1 * tw;
            outW[(size_t)row * 2 + 1] = p2 * tw;
        }
    }
}

// ---------------------------------------------------------------- launcher
extern "C" void kernel_launch(void* const* d_in, const int* in_sizes, int n_in,
                              void* d_out, int out_size) {
    const float* x = (const float*)d_in[0];   // [65536, 2048] fp32
    const float* W = (const float*)d_in[1];   // [64, 2048]   fp32
    float* out = (float*)d_out;

    static int configured = 0;
    if (!configured) {
        cudaFuncSetAttribute(router_mma_kernel,
                             cudaFuncAttributeMaxDynamicSharedMemorySize, SMEM_BYTES);
        configured = 1;
    }

    wsplit_kernel<<<(N_EXPERTS * IN_DIM) / 256, 256>>>(W);
    router_mma_kernel<<<GRID_CTAS, NTHREADS, SMEM_BYTES>>>(x, out);
}

// round 7
// speedup vs baseline: 1.5974x; 1.5974x over previous
#include <cuda_runtime.h>
#include <cuda_fp16.h>
#include <cstdint>

// ---------------------------------------------------------------- constants
#define N_TOKENS  65536
#define IN_DIM    2048
#define N_EXPERTS 64
#define TILE_M    256
#define BK        32
#define NITER     (IN_DIM / BK)       // 64
#define NTHREADS  256
#define GRID_CTAS (N_TOKENS / TILE_M) // 256

// smem stage layout (bytes). Row stride 40 halves = 80 B (20 words):
// 20*r mod 32 distinct for r=0..7 -> conflict-free ldmatrix.
// [ A_h1 256x80 | A_h2 256x80 | B_w1 64x80 | B_w2 64x80 ]
#define OFF_AR    20480
#define OFF_B1    40960
#define OFF_B2    46080
#define STAGE_B   51200
#define SMEM_BYTES (2 * STAGE_B)      // 102400 -> 1 CTA/SM

#define SPLIT_SCALE 2048.0f
#define INV_SCALE   (1.0f / 2048.0f)

// W pack: [chunk j=0..63][split 0..1][n=0..63][k=0..31] fp16 (512 KB)
// split0 = fp16(w), split1 = fp16((w - fp16(w)) * 2048)   (scaled: no subnormals)
__device__ __align__(16) __half Wpack_g[NITER * 2 * N_EXPERTS * BK];

// ---------------------------------------------------------------- helpers
__device__ __forceinline__ uint32_t smem_u32(const void* p) {
    uint32_t a;
    asm("{ .reg .u64 t; cvta.to.shared.u64 t, %1; cvt.u32.u64 %0, t; }" : "=r"(a) : "l"(p));
    return a;
}

__device__ __forceinline__ void ldsm4(uint32_t* r, uint32_t addr) {
    asm volatile("ldmatrix.sync.aligned.m8n8.x4.shared.b16 {%0,%1,%2,%3}, [%4];"
                 : "=r"(r[0]), "=r"(r[1]), "=r"(r[2]), "=r"(r[3]) : "r"(addr));
}

// fp32-accumulated main-bank MMA
__device__ __forceinline__ void mma_f32(float* c, const uint32_t* a,
                                        uint32_t b0, uint32_t b1) {
    asm volatile(
        "mma.sync.aligned.m16n8k16.row.col.f32.f16.f16.f32 "
        "{%0,%1,%2,%3}, {%4,%5,%6,%7}, {%8,%9}, {%0,%1,%2,%3};"
        : "+f"(c[0]), "+f"(c[1]), "+f"(c[2]), "+f"(c[3])
        : "r"(a[0]), "r"(a[1]), "r"(a[2]), "r"(a[3]), "r"(b0), "r"(b1));
}

// fp16-accumulated cross-bank MMA (2 C regs = 4 halves)
__device__ __forceinline__ void mma_f16(uint32_t* c, const uint32_t* a,
                                        uint32_t b0, uint32_t b1) {
    asm volatile(
        "mma.sync.aligned.m16n8k16.row.col.f16.f16.f16.f16 "
        "{%0,%1}, {%2,%3,%4,%5}, {%6,%7}, {%0,%1};"
        : "+r"(c[0]), "+r"(c[1])
        : "r"(a[0]), "r"(a[1]), "r"(a[2]), "r"(a[3]), "r"(b0), "r"(b1));
}

__device__ __forceinline__ void cp_async16(uint32_t dst, const void* src) {
    asm volatile("cp.async.ca.shared.global [%0], [%1], 16;" :: "r"(dst), "l"(src));
}
#define CP_COMMIT() asm volatile("cp.async.commit_group;" ::: "memory")
#define CP_WAIT0()  asm volatile("cp.async.wait_group 0;" ::: "memory")

// ---------------------------------------------------------------- W split pre-kernel
__global__ void wsplit_kernel(const float* __restrict__ W) {
    int idx = blockIdx.x * 256 + threadIdx.x;   // e*2048 + k
    int e = idx >> 11;
    int k = idx & 2047;
    float w = W[idx];
    __half h1 = __float2half_rn(w);
    float  r  = (w - __half2float(h1)) * SPLIT_SCALE;
    __half h2 = __float2half_rn(r);
    int j = k >> 5, kk = k & 31;
    Wpack_g[(size_t)j * 4096 + 0 * 2048 + e * 32 + kk] = h1;
    Wpack_g[(size_t)j * 4096 + 1 * 2048 + e * 32 + kk] = h2;
}

// ---------------------------------------------------------------- x conversion
// h1 = fp16(x); h2 = fp16((x - h1) * 2048)  -- scaled, stays in normal range
__device__ __forceinline__ void cvt_store(char* Ab, uint32_t off, float4 v) {
    __half2 h1a = __floats2half2_rn(v.x, v.y);
    __half2 h1b = __floats2half2_rn(v.z, v.w);
    float2 fa = __half22float2(h1a);
    float2 fb = __half22float2(h1b);
    __half2 ra = __floats2half2_rn((v.x - fa.x) * SPLIT_SCALE, (v.y - fa.y) * SPLIT_SCALE);
    __half2 rb = __floats2half2_rn((v.z - fb.x) * SPLIT_SCALE, (v.w - fb.y) * SPLIT_SCALE);
    uint2 hh, rr;
    hh.x = *(uint32_t*)&h1a; hh.y = *(uint32_t*)&h1b;
    rr.x = *(uint32_t*)&ra;  rr.y = *(uint32_t*)&rb;
    *(uint2*)(Ab + off)          = hh;
    *(uint2*)(Ab + OFF_AR + off) = rr;
}

// ---------------------------------------------------------------- main kernel
extern __shared__ __align__(16) char smch[];

__global__ void __launch_bounds__(NTHREADS, 1)
router_mma_kernel(const float* __restrict__ x, float* __restrict__ out) {
    const int tid  = threadIdx.x;
    const int w    = tid >> 5;
    const int lane = tid & 31;
    const int tokenBase = blockIdx.x * TILE_M;
    const uint32_t sb = smem_u32(smch);

    // ---- x LDG map: instr i covers rows w*32+i*4+(l>>3), float4 (l&7)
    //      -> each warp-LDG.128 touches 4 contiguous 128B lines.
    const float* xbase = x + (size_t)(tokenBase + w * 32 + (lane >> 3)) * IN_DIM
                           + (lane & 7) * 4;
    const uint32_t st_base = (uint32_t)((w * 32 + (lane >> 3)) * 80 + (lane & 7) * 8);

    // ---- W cp.async map
    const int wn  = (tid >> 2) & 63;
    const int wsk = tid & 3;
    const uint32_t b_dst0 = OFF_B1 + (uint32_t)wn * 80 + (uint32_t)wsk * 16;
    const uint32_t b_dst1 = OFF_B2 + (uint32_t)wn * 80 + (uint32_t)wsk * 16;

    // ---- ldmatrix offsets (stage-relative); warp owns rows [w*32, w*32+32)
    const uint32_t a_ld = (uint32_t)((w * 32 + (lane & 15)) * 80 + ((lane >> 4) & 1) * 16);
    const uint32_t b_ld = (uint32_t)(((lane & 7) + ((lane >> 4) & 1) * 8) * 80
                                     + ((lane >> 3) & 1) * 16);

    float    accM[2][32];    // fp32 main bank: h1*w1
    uint32_t accC[2][16];    // fp16 cross bank: h1*w2 + h2*w1 (cross units = x2048)
    #pragma unroll
    for (int m = 0; m < 2; m++) {
        #pragma unroll
        for (int i = 0; i < 32; i++) accM[m][i] = 0.0f;
        #pragma unroll
        for (int i = 0; i < 16; i++) accC[m][i] = 0u;
    }

    float4 xr[8];

    // ================= prologue: fill stage 0 =================
    {
        const char* wsrc = (const char*)Wpack_g;
        cp_async16(sb + b_dst0, wsrc + (size_t)tid * 16);
        cp_async16(sb + b_dst1, wsrc + (size_t)(tid + 256) * 16);
        CP_COMMIT();
        #pragma unroll
        for (int i = 0; i < 8; i++)
            xr[i] = *(const float4*)(xbase + (size_t)i * 4 * IN_DIM);
        char* Ab = smch;
        #pragma unroll
        for (int i = 0; i < 8; i++)
            cvt_store(Ab, st_base + (uint32_t)i * 320, xr[i]);
        CP_WAIT0();
        __syncthreads();
    }

    // ================= main loop =================
    for (int j = 0; j < NITER; j++) {
        const int s  = j & 1;
        const int nx = s ^ 1;
        const uint32_t stage = (uint32_t)s * STAGE_B;

        if (j + 1 < NITER) {
            const char* wsrc = (const char*)Wpack_g + (size_t)(j + 1) * 8192;
            const uint32_t nst = (uint32_t)nx * STAGE_B;
            cp_async16(sb + nst + b_dst0, wsrc + (size_t)tid * 16);
            cp_async16(sb + nst + b_dst1, wsrc + (size_t)(tid + 256) * 16);
            CP_COMMIT();
            #pragma unroll
            for (int i = 0; i < 8; i++)
                xr[i] = *(const float4*)(xbase + (size_t)i * 4 * IN_DIM + (j + 1) * BK);
        }

        // ---- compute stage s: load ALL frags, then 3 dependency-separated
        //      MMA phases (accC write distance 16 issues, accM once/kk) ----
        #pragma unroll
        for (int kk = 0; kk < 2; kk++) {
            const uint32_t ko = (uint32_t)kk * 32;
            uint32_t w1f[4][4], w2f[4][4], aH[2][4], aG[2][4];
            // loads ordered so earliest feed the first MMA phase
            #pragma unroll
            for (int g = 0; g < 4; g++)
                ldsm4(w1f[g], sb + stage + OFF_B1 + b_ld + (uint32_t)g * 1280 + ko);
            ldsm4(aH[0], sb + stage + a_ld + ko);
            ldsm4(aH[1], sb + stage + a_ld + 1280 + ko);
            #pragma unroll
            for (int g = 0; g < 4; g++)
                ldsm4(w2f[g], sb + stage + OFF_B2 + b_ld + (uint32_t)g * 1280 + ko);
            ldsm4(aG[0], sb + stage + OFF_AR + a_ld + ko);
            ldsm4(aG[1], sb + stage + OFF_AR + a_ld + 1280 + ko);

            // phase 1: fp32 main  (h1*w1)
            #pragma unroll
            for (int g = 0; g < 4; g++)
                #pragma unroll
                for (int m = 0; m < 2; m++) {
                    mma_f32(&accM[m][(2 * g) * 4],     aH[m], w1f[g][0], w1f[g][1]);
                    mma_f32(&accM[m][(2 * g + 1) * 4], aH[m], w1f[g][2], w1f[g][3]);
                }
            // phase 2: fp16 cross (h1*w2)
            #pragma unroll
            for (int g = 0; g < 4; g++)
                #pragma unroll
                for (int m = 0; m < 2; m++) {
                    mma_f16(&accC[m][(2 * g) * 2],     aH[m], w2f[g][0], w2f[g][1]);
                    mma_f16(&accC[m][(2 * g + 1) * 2], aH[m], w2f[g][2], w2f[g][3]);
                }
            // phase 3: fp16 cross (h2*w1) -- same accC regs, 16 issues later
            #pragma unroll
            for (int g = 0; g < 4; g++)
                #pragma unroll
                for (int m = 0; m < 2; m++) {
                    mma_f16(&accC[m][(2 * g) * 2],     aG[m], w1f[g][0], w1f[g][1]);
                    mma_f16(&accC[m][(2 * g + 1) * 2], aG[m], w1f[g][2], w1f[g][3]);
                }
        }

        if (j + 1 < NITER) {
            char* Ab = smch + (size_t)nx * STAGE_B;
            #pragma unroll
            for (int i = 0; i < 8; i++)
                cvt_store(Ab, st_base + (uint32_t)i * 320, xr[i]);
            CP_WAIT0();
        }
        __syncthreads();
    }

    // ================= epilogue =================
    const int q  = lane >> 2;   // row-in-8
    const int qc = lane & 3;    // column quad slot
    float* outIdx = out;
    float* outW   = out + 2 * (size_t)N_TOKENS;
    float* probs  = out + 4 * (size_t)N_TOKENS;

    #pragma unroll
    for (int m = 0; m < 2; m++) {
        #pragma unroll
        for (int r = 0; r < 2; r++) {
            // logits = main + cross/2048
            float v[16];
            #pragma unroll
            for (int f = 0; f < 8; f++) {
                uint32_t cr = accC[m][f * 2 + r];
                float2 cf = __half22float2(*(__half2*)&cr);
                v[2 * f]     = fmaf(cf.x, INV_SCALE, accM[m][f * 4 + 2 * r]);
                v[2 * f + 1] = fmaf(cf.y, INV_SCALE, accM[m][f * 4 + 2 * r + 1]);
            }
            // quad max
            float mx = v[0];
            #pragma unroll
            for (int i = 1; i < 16; i++) mx = fmaxf(mx, v[i]);
            mx = fmaxf(mx, __shfl_xor_sync(0xffffffffu, mx, 1));
            mx = fmaxf(mx, __shfl_xor_sync(0xffffffffu, mx, 2));

            // local top-2 on logits (e ascending within lane)
            float v1 = -3.4e38f, v2 = -3.4e38f;
            int   i1 = 0, i2 = 0;
            #pragma unroll
            for (int f = 0; f < 8; f++) {
                #pragma unroll
                for (int c = 0; c < 2; c++) {
                    float val = v[2 * f + c];
                    int   e   = f * 8 + qc * 2 + c;
                    if (val > v1)      { v2 = v1; i2 = i1; v1 = val; i1 = e; }
                    else if (val > v2) { v2 = val; i2 = e; }
                }
            }
            // quad merge (tie -> lower index, matching jax)
            #pragma unroll
            for (int d = 1; d <= 2; d <<= 1) {
                float ov1 = __shfl_xor_sync(0xffffffffu, v1, d);
                int   oi1 = __shfl_xor_sync(0xffffffffu, i1, d);
                float ov2 = __shfl_xor_sync(0xffffffffu, v2, d);
                int   oi2 = __shfl_xor_sync(0xffffffffu, i2, d);
                bool bet1 = (ov1 > v1) || (ov1 == v1 && oi1 < i1);
                if (bet1) {
                    bool keepOld = (v1 > ov2) || (v1 == ov2 && i1 < oi2);
                    if (keepOld) { v2 = v1; i2 = i1; } else { v2 = ov2; i2 = oi2; }
                    v1 = ov1; i1 = oi1;
                } else {
                    bool bet2 = (ov1 > v2) || (ov1 == v2 && oi1 < i2);
                    if (bet2) { v2 = ov1; i2 = oi1; }
                }
            }

            // exp + quad sum
            float ssum = 0.0f;
            #pragma unroll
            for (int i = 0; i < 16; i++) { v[i] = __expf(v[i] - mx); ssum += v[i]; }
            ssum += __shfl_xor_sync(0xffffffffu, ssum, 1);
            ssum += __shfl_xor_sync(0xffffffffu, ssum, 2);
            float rinv = 1.0f / ssum;

            const int row = tokenBase + w * 32 + m * 16 + q + r * 8;
            float* pr = probs + (size_t)row * N_EXPERTS + qc * 2;
            #pragma unroll
            for (int f = 0; f < 8; f++) {
                float2 pv = make_float2(v[2 * f] * rinv, v[2 * f + 1] * rinv);
                *(float2*)(pr + f * 8) = pv;
            }
            if (qc == 0) {
                float p1 = __expf(v1 - mx), p2 = __expf(v2 - mx);
                outIdx[(size_t)row * 2 + 0] = (float)i1;
                outIdx[(size_t)row * 2 + 1] = (float)i2;
                float tw = 1.0f / (p1 + p2);
                outW[(size_t)row * 2 + 0] = p1 * tw;
                outW[(size_t)row * 2 + 1] = p2 * tw;
            }
        }
    }
}

// ---------------------------------------------------------------- launcher
extern "C" void kernel_launch(void* const* d_in, const int* in_sizes, int n_in,
                              void* d_out, int out_size) {
    const float* x = (const float*)d_in[0];   // [65536, 2048] fp32
    const float* W = (const float*)d_in[1];   // [64, 2048]   fp32
    float* out = (float*)d_out;

    static int configured = 0;
    if (!configured) {
        cudaFuncSetAttribute(router_mma_kernel,
                             cudaFuncAttributeMaxDynamicSharedMemorySize, SMEM_BYTES);
        configured = 1;
    }

    wsplit_kernel<<<(N_EXPERTS * IN_DIM) / 256, 256>>>(W);
    router_mma_kernel<<<GRID_CTAS, NTHREADS, SMEM_BYTES>>>(x, out);
}

// round 8
// speedup vs baseline: 1.7177x; 1.0753x over previous
#include <cuda_runtime.h>
#include <cuda_fp16.h>
#include <cstdint>

// ---------------------------------------------------------------- constants
#define N_TOKENS  65536
#define IN_DIM    2048
#define N_EXPERTS 64
#define TILE_M    256
#define BK        32
#define NITER     (IN_DIM / BK)       // 64
#define GROUP     4                   // chunks per B group
#define NGROUPS   (NITER / GROUP)     // 16
#define NTHREADS  256
#define GRID_CTAS (N_TOKENS / TILE_M) // 256

// ---------------- smem map (bytes) ----------------
// A staging: warp-private 2-stage ring. Row stride 80 B (20 words):
//   stage s: h1 at s*40960 + row*80 ; h2 at s*40960 + 20480 + row*80
#define A_OFF_H2   20480
#define A_STAGE_B  40960
// B: 2 buffers x 4 chunks x (w1 64x80 | w2 64x80)
#define B_BASE     81920
#define B_CHUNK_B  10240
#define B_OFF_W2   5120
#define B_BUF_B    (GROUP * B_CHUNK_B)          // 40960
#define SMEM_BYTES (B_BASE + 2 * B_BUF_B)       // 163840 -> 1 CTA/SM

#define SPLIT_SCALE 2048.0f
#define INV_SCALE   (1.0f / 2048.0f)

// W pack: [chunk j=0..63][split 0..1][n=0..63][k=0..31] fp16 (512 KB)
// split0 = fp16(w), split1 = fp16((w - fp16(w)) * 2048)   (scaled: no subnormals)
__device__ __align__(16) __half Wpack_g[NITER * 2 * N_EXPERTS * BK];

// ---------------------------------------------------------------- helpers
__device__ __forceinline__ uint32_t smem_u32(const void* p) {
    uint32_t a;
    asm("{ .reg .u64 t; cvta.to.shared.u64 t, %1; cvt.u32.u64 %0, t; }" : "=r"(a) : "l"(p));
    return a;
}

__device__ __forceinline__ void ldsm4(uint32_t* r, uint32_t addr) {
    asm volatile("ldmatrix.sync.aligned.m8n8.x4.shared.b16 {%0,%1,%2,%3}, [%4];"
                 : "=r"(r[0]), "=r"(r[1]), "=r"(r[2]), "=r"(r[3]) : "r"(addr));
}

// fp32-accumulated main-bank MMA
__device__ __forceinline__ void mma_f32(float* c, const uint32_t* a,
                                        uint32_t b0, uint32_t b1) {
    asm volatile(
        "mma.sync.aligned.m16n8k16.row.col.f32.f16.f16.f32 "
        "{%0,%1,%2,%3}, {%4,%5,%6,%7}, {%8,%9}, {%0,%1,%2,%3};"
        : "+f"(c[0]), "+f"(c[1]), "+f"(c[2]), "+f"(c[3])
        : "r"(a[0]), "r"(a[1]), "r"(a[2]), "r"(a[3]), "r"(b0), "r"(b1));
}

// fp16-accumulated cross-bank MMA (2 C regs = 4 halves)
__device__ __forceinline__ void mma_f16(uint32_t* c, const uint32_t* a,
                                        uint32_t b0, uint32_t b1) {
    asm volatile(
        "mma.sync.aligned.m16n8k16.row.col.f16.f16.f16.f16 "
        "{%0,%1}, {%2,%3,%4,%5}, {%6,%7}, {%0,%1};"
        : "+r"(c[0]), "+r"(c[1])
        : "r"(a[0]), "r"(a[1]), "r"(a[2]), "r"(a[3]), "r"(b0), "r"(b1));
}

__device__ __forceinline__ void cp_async16(uint32_t dst, const void* src) {
    asm volatile("cp.async.ca.shared.global [%0], [%1], 16;" :: "r"(dst), "l"(src));
}
#define CP_COMMIT() asm volatile("cp.async.commit_group;" ::: "memory")
#define CP_WAIT0()  asm volatile("cp.async.wait_group 0;" ::: "memory")

// ---------------------------------------------------------------- W split pre-kernel
__global__ void wsplit_kernel(const float* __restrict__ W) {
    int idx = blockIdx.x * 256 + threadIdx.x;   // e*2048 + k
    int e = idx >> 11;
    int k = idx & 2047;
    float w = W[idx];
    __half h1 = __float2half_rn(w);
    float  r  = (w - __half2float(h1)) * SPLIT_SCALE;
    __half h2 = __float2half_rn(r);
    int j = k >> 5, kk = k & 31;
    Wpack_g[(size_t)j * 4096 + 0 * 2048 + e * 32 + kk] = h1;
    Wpack_g[(size_t)j * 4096 + 1 * 2048 + e * 32 + kk] = h2;
}

// ---------------------------------------------------------------- x conversion
// h1 = fp16(x); h2 = fp16((x - h1) * 2048)  -- scaled, stays in normal range
__device__ __forceinline__ void cvt_store(char* Ab, uint32_t off, float4 v) {
    __half2 h1a = __floats2half2_rn(v.x, v.y);
    __half2 h1b = __floats2half2_rn(v.z, v.w);
    float2 fa = __half22float2(h1a);
    float2 fb = __half22float2(h1b);
    __half2 ra = __floats2half2_rn((v.x - fa.x) * SPLIT_SCALE, (v.y - fa.y) * SPLIT_SCALE);
    __half2 rb = __floats2half2_rn((v.z - fb.x) * SPLIT_SCALE, (v.w - fb.y) * SPLIT_SCALE);
    uint2 hh, rr;
    hh.x = *(uint32_t*)&h1a; hh.y = *(uint32_t*)&h1b;
    rr.x = *(uint32_t*)&ra;  rr.y = *(uint32_t*)&rb;
    *(uint2*)(Ab + off)            = hh;
    *(uint2*)(Ab + A_OFF_H2 + off) = rr;
}

// ---------------------------------------------------------------- main kernel
extern __shared__ __align__(16) char smch[];

__global__ void __launch_bounds__(NTHREADS, 1)
router_mma_kernel(const float* __restrict__ x, float* __restrict__ out) {
    const int tid  = threadIdx.x;
    const int w    = tid >> 5;
    const int lane = tid & 31;
    const int tokenBase = blockIdx.x * TILE_M;
    const uint32_t sb = smem_u32(smch);

    // ---- x LDG map: instr i covers rows w*32+i*4+(l>>3), float4 (l&7)
    const float* xbase = x + (size_t)(tokenBase + w * 32 + (lane >> 3)) * IN_DIM
                           + (lane & 7) * 4;
    const uint32_t st_base = (uint32_t)((w * 32 + (lane >> 3)) * 80 + (lane & 7) * 8);

    // ---- B cp.async map: 8 segs/thread/group; gs = tid + 256*i
    //      c = gs>>9, split = (gs>>8)&1, seg = gs&255, n = seg>>2, k16 = seg&3
    // ---- ldmatrix offsets
    const uint32_t a_ld = (uint32_t)((w * 32 + (lane & 15)) * 80 + ((lane >> 4) & 1) * 16);
    const uint32_t b_ld = (uint32_t)(((lane & 7) + ((lane >> 4) & 1) * 8) * 80
                                     + ((lane >> 3) & 1) * 16);

    float    accM[2][32];    // fp32 main bank: h1*w1
    uint32_t accC[2][16];    // fp16 cross bank: h1*w2 + h2*w1 (x2048 units)
    #pragma unroll
    for (int m = 0; m < 2; m++) {
        #pragma unroll
        for (int i = 0; i < 32; i++) accM[m][i] = 0.0f;
        #pragma unroll
        for (int i = 0; i < 16; i++) accC[m][i] = 0u;
    }

    float4 xr[8];

    // ================= prologue =================
    {
        // B group 0 -> buffer 0
        #pragma unroll
        for (int i = 0; i < 8; i++) {
            int gs    = tid + 256 * i;
            int c     = gs >> 9;
            int split = (gs >> 8) & 1;
            int seg   = gs & 255;
            uint32_t dst = B_BASE + (uint32_t)c * B_CHUNK_B + (uint32_t)split * B_OFF_W2
                         + (uint32_t)(seg >> 2) * 80 + (uint32_t)(seg & 3) * 16;
            const char* src = (const char*)Wpack_g + (size_t)c * 8192
                            + (size_t)split * 4096 + (size_t)seg * 16;
            cp_async16(sb + dst, src);
        }
        CP_COMMIT();
        // A chunk 0 -> stage 0 (warp-private)
        #pragma unroll
        for (int i = 0; i < 8; i++)
            xr[i] = *(const float4*)(xbase + (size_t)i * 4 * IN_DIM);
        #pragma unroll
        for (int i = 0; i < 8; i++)
            cvt_store(smch, st_base + (uint32_t)i * 320, xr[i]);
        CP_WAIT0();
        __syncthreads();
    }

    // ================= main loop: 16 groups x 4 chunks =================
    for (int g = 0; g < NGROUPS; g++) {
        // issue next B group into the other buffer
        if (g + 1 < NGROUPS) {
            const uint32_t nbuf = B_BASE + (uint32_t)((g + 1) & 1) * B_BUF_B;
            const char* gsrc = (const char*)Wpack_g + (size_t)(g + 1) * GROUP * 8192;
            #pragma unroll
            for (int i = 0; i < 8; i++) {
                int gs    = tid + 256 * i;
                int c     = gs >> 9;
                int split = (gs >> 8) & 1;
                int seg   = gs & 255;
                uint32_t dst = nbuf + (uint32_t)c * B_CHUNK_B + (uint32_t)split * B_OFF_W2
                             + (uint32_t)(seg >> 2) * 80 + (uint32_t)(seg & 3) * 16;
                cp_async16(sb + dst, gsrc + (size_t)c * 8192 + (size_t)split * 4096
                                          + (size_t)seg * 16);
            }
            CP_COMMIT();
        }

        const uint32_t bbuf = B_BASE + (uint32_t)(g & 1) * B_BUF_B;

        #pragma unroll
        for (int c = 0; c < GROUP; c++) {
            const int jj = g * GROUP + c;
            const uint32_t astage = (uint32_t)(jj & 1) * A_STAGE_B;
            const uint32_t bchunk = bbuf + (uint32_t)c * B_CHUNK_B;

            // prefetch next x chunk (warp-private)
            if (jj + 1 < NITER) {
                #pragma unroll
                for (int i = 0; i < 8; i++)
                    xr[i] = *(const float4*)(xbase + (size_t)i * 4 * IN_DIM
                                                   + (size_t)(jj + 1) * BK);
            }

            // ---- compute chunk jj ----
            #pragma unroll
            for (int kk = 0; kk < 2; kk++) {
                const uint32_t ko = (uint32_t)kk * 32;
                uint32_t w1f[4][4], w2f[4][4], aH[2][4], aG[2][4];
                #pragma unroll
                for (int gg = 0; gg < 4; gg++)
                    ldsm4(w1f[gg], sb + bchunk + b_ld + (uint32_t)gg * 1280 + ko);
                ldsm4(aH[0], sb + astage + a_ld + ko);
                ldsm4(aH[1], sb + astage + a_ld + 1280 + ko);
                #pragma unroll
                for (int gg = 0; gg < 4; gg++)
                    ldsm4(w2f[gg], sb + bchunk + B_OFF_W2 + b_ld + (uint32_t)gg * 1280 + ko);
                ldsm4(aG[0], sb + astage + A_OFF_H2 + a_ld + ko);
                ldsm4(aG[1], sb + astage + A_OFF_H2 + a_ld + 1280 + ko);

                #pragma unroll
                for (int gg = 0; gg < 4; gg++)
                    #pragma unroll
                    for (int m = 0; m < 2; m++) {
                        mma_f32(&accM[m][(2 * gg) * 4],     aH[m], w1f[gg][0], w1f[gg][1]);
                        mma_f32(&accM[m][(2 * gg + 1) * 4], aH[m], w1f[gg][2], w1f[gg][3]);
                    }
                #pragma unroll
                for (int gg = 0; gg < 4; gg++)
                    #pragma unroll
                    for (int m = 0; m < 2; m++) {
                        mma_f16(&accC[m][(2 * gg) * 2],     aH[m], w2f[gg][0], w2f[gg][1]);
                        mma_f16(&accC[m][(2 * gg + 1) * 2], aH[m], w2f[gg][2], w2f[gg][3]);
                    }
                #pragma unroll
                for (int gg = 0; gg < 4; gg++)
                    #pragma unroll
                    for (int m = 0; m < 2; m++) {
                        mma_f16(&accC[m][(2 * gg) * 2],     aG[m], w1f[gg][0], w1f[gg][1]);
                        mma_f16(&accC[m][(2 * gg + 1) * 2], aG[m], w1f[gg][2], w1f[gg][3]);
                    }
            }

            // stage next A chunk (warp-private -> only __syncwarp needed)
            if (jj + 1 < NITER) {
                char* Ab = smch + (size_t)((jj + 1) & 1) * A_STAGE_B;
                #pragma unroll
                for (int i = 0; i < 8; i++)
                    cvt_store(Ab, st_base + (uint32_t)i * 320, xr[i]);
            }
            __syncwarp();
        }

        // B[g+1] must have landed; everyone done reading B buffer (g&1)
        CP_WAIT0();
        __syncthreads();
    }

    // ================= epilogue =================
    const int q  = lane >> 2;   // row-in-8
    const int qc = lane & 3;    // column quad slot
    float* outIdx = out;
    float* outW   = out + 2 * (size_t)N_TOKENS;
    float* probs  = out + 4 * (size_t)N_TOKENS;

    #pragma unroll
    for (int m = 0; m < 2; m++) {
        #pragma unroll
        for (int r = 0; r < 2; r++) {
            // logits = main + cross/2048
            float v[16];
            #pragma unroll
            for (int f = 0; f < 8; f++) {
                uint32_t cr = accC[m][f * 2 + r];
                float2 cf = __half22float2(*(__half2*)&cr);
                v[2 * f]     = fmaf(cf.x, INV_SCALE, accM[m][f * 4 + 2 * r]);
                v[2 * f + 1] = fmaf(cf.y, INV_SCALE, accM[m][f * 4 + 2 * r + 1]);
            }
            // quad max
            float mx = v[0];
            #pragma unroll
            for (int i = 1; i < 16; i++) mx = fmaxf(mx, v[i]);
            mx = fmaxf(mx, __shfl_xor_sync(0xffffffffu, mx, 1));
            mx = fmaxf(mx, __shfl_xor_sync(0xffffffffu, mx, 2));

            // local top-2 on logits (e ascending within lane)
            float v1 = -3.4e38f, v2 = -3.4e38f;
            int   i1 = 0, i2 = 0;
            #pragma unroll
            for (int f = 0; f < 8; f++) {
                #pragma unroll
                for (int cch = 0; cch < 2; cch++) {
                    float val = v[2 * f + cch];
                    int   e   = f * 8 + qc * 2 + cch;
                    if (val > v1)      { v2 = v1; i2 = i1; v1 = val; i1 = e; }
                    else if (val > v2) { v2 = val; i2 = e; }
                }
            }
            // quad merge (tie -> lower index, matching jax)
            #pragma unroll
            for (int d = 1; d <= 2; d <<= 1) {
                float ov1 = __shfl_xor_sync(0xffffffffu, v1, d);
                int   oi1 = __shfl_xor_sync(0xffffffffu, i1, d);
                float ov2 = __shfl_xor_sync(0xffffffffu, v2, d);
                int   oi2 = __shfl_xor_sync(0xffffffffu, i2, d);
                bool bet1 = (ov1 > v1) || (ov1 == v1 && oi1 < i1);
                if (bet1) {
                    bool keepOld = (v1 > ov2) || (v1 == ov2 && i1 < oi2);
                    if (keepOld) { v2 = v1; i2 = i1; } else { v2 = ov2; i2 = oi2; }
                    v1 = ov1; i1 = oi1;
                } else {
                    bool bet2 = (ov1 > v2) || (ov1 == v2 && oi1 < i2);
                    if (bet2) { v2 = ov1; i2 = oi1; }
                }
            }

            // exp + quad sum
            float ssum = 0.0f;
            #pragma unroll
            for (int i = 0; i < 16; i++) { v[i] = __expf(v[i] - mx); ssum += v[i]; }
            ssum += __shfl_xor_sync(0xffffffffu, ssum, 1);
            ssum += __shfl_xor_sync(0xffffffffu, ssum, 2);
            float rinv = 1.0f / ssum;

            const int row = tokenBase + w * 32 + m * 16 + q + r * 8;
            float* pr = probs + (size_t)row * N_EXPERTS + qc * 2;
            #pragma unroll
            for (int f = 0; f < 8; f++) {
                float2 pv = make_float2(v[2 * f] * rinv, v[2 * f + 1] * rinv);
                *(float2*)(pr + f * 8) = pv;
            }
            if (qc == 0) {
                float p1 = __expf(v1 - mx), p2 = __expf(v2 - mx);
                outIdx[(size_t)row * 2 + 0] = (float)i1;
                outIdx[(size_t)row * 2 + 1] = (float)i2;
                float tw = 1.0f / (p1 + p2);
                outW[(size_t)row * 2 + 0] = p1 * tw;
                outW[(size_t)row * 2 + 1] = p2 * tw;
            }
        }
    }
}

// ---------------------------------------------------------------- launcher
extern "C" void kernel_launch(void* const* d_in, const int* in_sizes, int n_in,
                              void* d_out, int out_size) {
    const float* x = (const float*)d_in[0];   // [65536, 2048] fp32
    const float* W = (const float*)d_in[1];   // [64, 2048]   fp32
    float* out = (float*)d_out;

    static int configured = 0;
    if (!configured) {
        cudaFuncSetAttribute(router_mma_kernel,
                             cudaFuncAttributeMaxDynamicSharedMemorySize, SMEM_BYTES);
        configured = 1;
    }

    wsplit_kernel<<<(N_EXPERTS * IN_DIM) / 256, 256>>>(W);
    router_mma_kernel<<<GRID_CTAS, NTHREADS, SMEM_BYTES>>>(x, out);
}